// round 5
// baseline (speedup 1.0000x reference)
#include <cuda_runtime.h>

#define S_LEN  2048
#define NHEADS 12
#define DMODEL 768
#define HD     64
#define MTOT   8192  // B * S

// Scratch for Q, K, V projections (allocation-free rule: __device__ globals)
__device__ float gQ[(size_t)MTOT * DMODEL];
__device__ float gK[(size_t)MTOT * DMODEL];
__device__ float gV[(size_t)MTOT * DMODEL];

// ---------------------------------------------------------------------------
// Fused QKV projection: out[z] = toks @ W[z] + b[z]
// M=8192, N=768, K=768. Block tile 128x64, BK=16, 256 threads, 8x4 per thread.
// ---------------------------------------------------------------------------
__global__ __launch_bounds__(256)
void qkv_gemm_kernel(const float* __restrict__ toks,
                     const float* __restrict__ Wq, const float* __restrict__ bq,
                     const float* __restrict__ Wk, const float* __restrict__ bk,
                     const float* __restrict__ Wv, const float* __restrict__ bv)
{
    const int z = blockIdx.z;
    const float* __restrict__ W    = (z == 0) ? Wq : (z == 1) ? Wk : Wv;
    const float* __restrict__ bias = (z == 0) ? bq : (z == 1) ? bk : bv;
    float* __restrict__ outp       = (z == 0) ? gQ : (z == 1) ? gK : gV;

    const int m0  = blockIdx.x * 128;
    const int n0  = blockIdx.y * 64;
    const int tid = threadIdx.x;
    const int tx  = tid & 15;   // 0..15 -> 4 N-cols
    const int ty  = tid >> 4;   // 0..15 -> 8 M-rows

    __shared__ __align__(16) float As[16][132];  // [k][m], padded (2-way max)
    __shared__ __align__(16) float Bs[16][64];   // [k][n]

    float acc[8][4];
    #pragma unroll
    for (int i = 0; i < 8; i++)
        #pragma unroll
        for (int j = 0; j < 4; j++) acc[i][j] = 0.f;

    for (int k0 = 0; k0 < DMODEL; k0 += 16) {
        // Load A tile 128x16 (transposed into smem)
        #pragma unroll
        for (int it = 0; it < 2; it++) {
            int idx = tid + it * 256;        // 0..511 float4s
            int row = idx >> 2;              // 0..127
            int c4  = idx & 3;               // 0..3
            float4 v = *(const float4*)(toks + (size_t)(m0 + row) * DMODEL + k0 + c4 * 4);
            As[c4 * 4 + 0][row] = v.x;
            As[c4 * 4 + 1][row] = v.y;
            As[c4 * 4 + 2][row] = v.z;
            As[c4 * 4 + 3][row] = v.w;
        }
        // Load B tile 16x64
        {
            int row = tid >> 4;              // 0..15
            int c4  = tid & 15;              // 0..15
            *(float4*)&Bs[row][c4 * 4] =
                *(const float4*)(W + (size_t)(k0 + row) * DMODEL + n0 + c4 * 4);
        }
        __syncthreads();

        #pragma unroll
        for (int kk = 0; kk < 16; kk++) {
            float4 b4 = *(float4*)&Bs[kk][tx * 4];
            float4 a0 = *(float4*)&As[kk][ty * 8];
            float4 a1 = *(float4*)&As[kk][ty * 8 + 4];
            float a[8] = {a0.x, a0.y, a0.z, a0.w, a1.x, a1.y, a1.z, a1.w};
            float bb[4] = {b4.x, b4.y, b4.z, b4.w};
            #pragma unroll
            for (int i = 0; i < 8; i++)
                #pragma unroll
                for (int j = 0; j < 4; j++)
                    acc[i][j] = fmaf(a[i], bb[j], acc[i][j]);
        }
        __syncthreads();
    }

    float4 b4 = *(const float4*)(bias + n0 + tx * 4);
    #pragma unroll
    for (int i = 0; i < 8; i++) {
        float4 r;
        r.x = acc[i][0] + b4.x;
        r.y = acc[i][1] + b4.y;
        r.z = acc[i][2] + b4.z;
        r.w = acc[i][3] + b4.w;
        *(float4*)(outp + (size_t)(m0 + ty * 8 + i) * DMODEL + n0 + tx * 4) = r;
    }
}

// ---------------------------------------------------------------------------
// Flash attention, fp32. One CTA per (b, h, 64-row q tile).
// 256 threads as 16x16: thread (ty,tx) owns q-rows ty*4..+3, k/hd cols tx*4..+3.
// Online softmax state (m, l) kept redundantly per-thread (identical across tx
// after the butterfly reductions). P tile aliases the K smem buffer.
// ---------------------------------------------------------------------------
#define LDP 68  // padded row stride (floats) for 64-wide smem tiles

__global__ __launch_bounds__(256, 2)
void attn_kernel(const int* __restrict__ masks, float* __restrict__ outp)
{
    extern __shared__ __align__(16) float sm[];
    float* Qs = sm;                // 64 x LDP  (Q, pre-scaled by 1/8)
    float* Ks = sm + 64 * LDP;     // 64 x LDP  (K tile; later aliased as P)
    float* Vs = sm + 2 * 64 * LDP; // 64 x LDP  (V tile)

    const int tid = threadIdx.x;
    const int tx  = tid & 15;
    const int ty  = tid >> 4;
    const int q0  = blockIdx.x * 64;
    const int h   = blockIdx.y;
    const int b   = blockIdx.z;
    const int r0  = ty * 4;
    const int c0  = tx * 4;

    const size_t base = (size_t)b * S_LEN * DMODEL + (size_t)h * HD;

    // Load Q tile, fold in 1/sqrt(64) = 0.125
    #pragma unroll
    for (int t = 0; t < 4; t++) {
        int idx = tid + t * 256;
        int r = idx >> 4, d4 = idx & 15;
        float4 v = *(const float4*)(gQ + base + (size_t)(q0 + r) * DMODEL + d4 * 4);
        v.x *= 0.125f; v.y *= 0.125f; v.z *= 0.125f; v.w *= 0.125f;
        *(float4*)&Qs[r * LDP + d4 * 4] = v;
    }

    int mrow[4];
    #pragma unroll
    for (int i = 0; i < 4; i++) mrow[i] = masks[b * S_LEN + q0 + r0 + i];

    float m_run[4], l_run[4], acc[4][4];
    #pragma unroll
    for (int i = 0; i < 4; i++) {
        m_run[i] = -3.0e38f;
        l_run[i] = 0.f;
        #pragma unroll
        for (int j = 0; j < 4; j++) acc[i][j] = 0.f;
    }

    for (int k0 = 0; k0 < S_LEN; k0 += 64) {
        __syncthreads();  // prior iteration done with Ks(=P) and Vs
        #pragma unroll
        for (int t = 0; t < 4; t++) {
            int idx = tid + t * 256;
            int r = idx >> 4, d4 = idx & 15;
            size_t g = base + (size_t)(k0 + r) * DMODEL + d4 * 4;
            *(float4*)&Ks[r * LDP + d4 * 4] = *(const float4*)(gK + g);
            *(float4*)&Vs[r * LDP + d4 * 4] = *(const float4*)(gV + g);
        }
        __syncthreads();

        int mcol[4];
        #pragma unroll
        for (int j = 0; j < 4; j++) mcol[j] = masks[b * S_LEN + k0 + c0 + j];

        // S = Q . K^T  (4x4 per thread)
        float s[4][4];
        #pragma unroll
        for (int i = 0; i < 4; i++)
            #pragma unroll
            for (int j = 0; j < 4; j++) s[i][j] = 0.f;

        #pragma unroll 4
        for (int kk = 0; kk < HD; kk += 4) {
            float4 qa[4], kb[4];
            #pragma unroll
            for (int i = 0; i < 4; i++) qa[i] = *(float4*)&Qs[(r0 + i) * LDP + kk];
            #pragma unroll
            for (int j = 0; j < 4; j++) kb[j] = *(float4*)&Ks[(c0 + j) * LDP + kk];
            #pragma unroll
            for (int i = 0; i < 4; i++)
                #pragma unroll
                for (int j = 0; j < 4; j++) {
                    s[i][j] = fmaf(qa[i].x, kb[j].x, s[i][j]);
                    s[i][j] = fmaf(qa[i].y, kb[j].y, s[i][j]);
                    s[i][j] = fmaf(qa[i].z, kb[j].z, s[i][j]);
                    s[i][j] = fmaf(qa[i].w, kb[j].w, s[i][j]);
                }
        }

        // Mask: exactly reproduces reference fp32 (-1e31 absorbs the score)
        #pragma unroll
        for (int i = 0; i < 4; i++)
            #pragma unroll
            for (int j = 0; j < 4; j++)
                if (!(mrow[i] & mcol[j])) s[i][j] = -1e31f;

        // Row max across 64 keys: local 4, then butterfly over the 16 tx lanes
        float rmax[4];
        #pragma unroll
        for (int i = 0; i < 4; i++)
            rmax[i] = fmaxf(fmaxf(s[i][0], s[i][1]), fmaxf(s[i][2], s[i][3]));
        #pragma unroll
        for (int msk = 1; msk < 16; msk <<= 1)
            #pragma unroll
            for (int i = 0; i < 4; i++)
                rmax[i] = fmaxf(rmax[i], __shfl_xor_sync(0xffffffffu, rmax[i], msk));

        float p[4][4], rsum[4], scl[4];
        #pragma unroll
        for (int i = 0; i < 4; i++) {
            float mn = fmaxf(m_run[i], rmax[i]);
            scl[i]   = __expf(m_run[i] - mn);
            m_run[i] = mn;
            float sr = 0.f;
            #pragma unroll
            for (int j = 0; j < 4; j++) {
                p[i][j] = __expf(s[i][j] - mn);
                sr += p[i][j];
            }
            rsum[i] = sr;
        }
        #pragma unroll
        for (int msk = 1; msk < 16; msk <<= 1)
            #pragma unroll
            for (int i = 0; i < 4; i++)
                rsum[i] += __shfl_xor_sync(0xffffffffu, rsum[i], msk);
        #pragma unroll
        for (int i = 0; i < 4; i++) {
            l_run[i] = l_run[i] * scl[i] + rsum[i];
            #pragma unroll
            for (int j = 0; j < 4; j++) acc[i][j] *= scl[i];
        }

        __syncthreads();  // everyone done reading Ks as K
        #pragma unroll
        for (int i = 0; i < 4; i++) {
            float4 pv = make_float4(p[i][0], p[i][1], p[i][2], p[i][3]);
            *(float4*)&Ks[(r0 + i) * LDP + c0] = pv;  // Ks now holds P
        }
        __syncthreads();

        // acc += P . V
        #pragma unroll 4
        for (int kk = 0; kk < 64; kk += 4) {
            float4 pa[4], vb[4];
            #pragma unroll
            for (int i = 0; i < 4; i++) pa[i] = *(float4*)&Ks[(r0 + i) * LDP + kk];
            #pragma unroll
            for (int l = 0; l < 4; l++) vb[l] = *(float4*)&Vs[(kk + l) * LDP + c0];
            #pragma unroll
            for (int i = 0; i < 4; i++) {
                acc[i][0] = fmaf(pa[i].x, vb[0].x, acc[i][0]);
                acc[i][0] = fmaf(pa[i].y, vb[1].x, acc[i][0]);
                acc[i][0] = fmaf(pa[i].z, vb[2].x, acc[i][0]);
                acc[i][0] = fmaf(pa[i].w, vb[3].x, acc[i][0]);
                acc[i][1] = fmaf(pa[i].x, vb[0].y, acc[i][1]);
                acc[i][1] = fmaf(pa[i].y, vb[1].y, acc[i][1]);
                acc[i][1] = fmaf(pa[i].z, vb[2].y, acc[i][1]);
                acc[i][1] = fmaf(pa[i].w, vb[3].y, acc[i][1]);
                acc[i][2] = fmaf(pa[i].x, vb[0].z, acc[i][2]);
                acc[i][2] = fmaf(pa[i].y, vb[1].z, acc[i][2]);
                acc[i][2] = fmaf(pa[i].z, vb[2].z, acc[i][2]);
                acc[i][2] = fmaf(pa[i].w, vb[3].z, acc[i][2]);
                acc[i][3] = fmaf(pa[i].x, vb[0].w, acc[i][3]);
                acc[i][3] = fmaf(pa[i].y, vb[1].w, acc[i][3]);
                acc[i][3] = fmaf(pa[i].z, vb[2].w, acc[i][3]);
                acc[i][3] = fmaf(pa[i].w, vb[3].w, acc[i][3]);
            }
        }
    }

    // Epilogue: ctx = acc / l, write to [b, s, h*64 + d] layout
    #pragma unroll
    for (int i = 0; i < 4; i++) {
        float inv = 1.0f / l_run[i];
        float4 r;
        r.x = acc[i][0] * inv;
        r.y = acc[i][1] * inv;
        r.z = acc[i][2] * inv;
        r.w = acc[i][3] * inv;
        *(float4*)(outp + (size_t)(b * S_LEN + q0 + r0 + i) * DMODEL + h * HD + c0) = r;
    }
}

// ---------------------------------------------------------------------------
extern "C" void kernel_launch(void* const* d_in, const int* in_sizes, int n_in,
                              void* d_out, int out_size)
{
    (void)in_sizes; (void)n_in; (void)out_size;
    const float* toks  = (const float*)d_in[0];
    const int*   masks = (const int*)  d_in[1];
    const float* Wq    = (const float*)d_in[2];
    const float* bq    = (const float*)d_in[3];
    const float* Wk    = (const float*)d_in[4];
    const float* bk    = (const float*)d_in[5];
    const float* Wv    = (const float*)d_in[6];
    const float* bv    = (const float*)d_in[7];
    float* outp = (float*)d_out;

    const int smem_bytes = 3 * 64 * LDP * sizeof(float);  // 52224 > 48K default
    cudaFuncSetAttribute(attn_kernel,
                         cudaFuncAttributeMaxDynamicSharedMemorySize, smem_bytes);

    qkv_gemm_kernel<<<dim3(64, 12, 3), 256>>>(toks, Wq, bq, Wk, bk, Wv, bv);
    attn_kernel<<<dim3(32, 12, 4), 256, smem_bytes>>>(masks, outp);
}

// round 8
// speedup vs baseline: 1.5038x; 1.5038x over previous
#include <cuda_runtime.h>

#define S_LEN  2048
#define NHEADS 12
#define DMODEL 768
#define HD     64
#define MTOT   8192  // B * S

#define QT 128   // q rows per CTA
#define KT 64    // keys per tile
#define LDS_ 68  // padded row stride (floats), 16B-aligned

// Scratch for Q, K, V projections (allocation-free rule: __device__ globals)
__device__ float gQ[(size_t)MTOT * DMODEL];
__device__ float gK[(size_t)MTOT * DMODEL];
__device__ float gV[(size_t)MTOT * DMODEL];

// ---------------------------------------------------------------------------
// Fused QKV projection: out[z] = toks @ W[z] + b[z]
// M=8192, N=768, K=768. Block tile 128x64, BK=16, 256 threads, 8x4 per thread.
// (~80% of fp32 FMA floor already; untouched this round.)
// ---------------------------------------------------------------------------
__global__ __launch_bounds__(256)
void qkv_gemm_kernel(const float* __restrict__ toks,
                     const float* __restrict__ Wq, const float* __restrict__ bq,
                     const float* __restrict__ Wk, const float* __restrict__ bk,
                     const float* __restrict__ Wv, const float* __restrict__ bv)
{
    const int z = blockIdx.z;
    const float* __restrict__ W    = (z == 0) ? Wq : (z == 1) ? Wk : Wv;
    const float* __restrict__ bias = (z == 0) ? bq : (z == 1) ? bk : bv;
    float* __restrict__ outp       = (z == 0) ? gQ : (z == 1) ? gK : gV;

    const int m0  = blockIdx.x * 128;
    const int n0  = blockIdx.y * 64;
    const int tid = threadIdx.x;
    const int tx  = tid & 15;
    const int ty  = tid >> 4;

    __shared__ __align__(16) float As[16][132];
    __shared__ __align__(16) float Bs[16][64];

    float acc[8][4];
    #pragma unroll
    for (int i = 0; i < 8; i++)
        #pragma unroll
        for (int j = 0; j < 4; j++) acc[i][j] = 0.f;

    for (int k0 = 0; k0 < DMODEL; k0 += 16) {
        #pragma unroll
        for (int it = 0; it < 2; it++) {
            int idx = tid + it * 256;
            int row = idx >> 2;
            int c4  = idx & 3;
            float4 v = *(const float4*)(toks + (size_t)(m0 + row) * DMODEL + k0 + c4 * 4);
            As[c4 * 4 + 0][row] = v.x;
            As[c4 * 4 + 1][row] = v.y;
            As[c4 * 4 + 2][row] = v.z;
            As[c4 * 4 + 3][row] = v.w;
        }
        {
            int row = tid >> 4;
            int c4  = tid & 15;
            *(float4*)&Bs[row][c4 * 4] =
                *(const float4*)(W + (size_t)(k0 + row) * DMODEL + n0 + c4 * 4);
        }
        __syncthreads();

        #pragma unroll
        for (int kk = 0; kk < 16; kk++) {
            float4 b4 = *(float4*)&Bs[kk][tx * 4];
            float4 a0 = *(float4*)&As[kk][ty * 8];
            float4 a1 = *(float4*)&As[kk][ty * 8 + 4];
            float a[8] = {a0.x, a0.y, a0.z, a0.w, a1.x, a1.y, a1.z, a1.w};
            float bb[4] = {b4.x, b4.y, b4.z, b4.w};
            #pragma unroll
            for (int i = 0; i < 8; i++)
                #pragma unroll
                for (int j = 0; j < 4; j++)
                    acc[i][j] = fmaf(a[i], bb[j], acc[i][j]);
        }
        __syncthreads();
    }

    float4 b4 = *(const float4*)(bias + n0 + tx * 4);
    #pragma unroll
    for (int i = 0; i < 8; i++) {
        float4 r;
        r.x = acc[i][0] + b4.x;
        r.y = acc[i][1] + b4.y;
        r.z = acc[i][2] + b4.z;
        r.w = acc[i][3] + b4.w;
        *(float4*)(outp + (size_t)(m0 + ty * 8 + i) * DMODEL + n0 + tx * 4) = r;
    }
}

// ---------------------------------------------------------------------------
// Flash attention v2, fp32. CTA = (b, h, 128-row q tile), 64-key tiles.
// 256 threads: ty = tid>>4 owns 8 q-rows (r0=ty*8), tx = tid&15 owns
// 4 keys (QK/P stages) or 4 hd-cols (PV stage), c0 = tx*4.
//
// Conflict-free mainloop smem:
//   Qs  [128][68] row-major  -> qa addr depends on ty only  => broadcast
//   KsT [ 64][68] d-major,   -> kb contiguous across tx     => conflict-free
//        key-groups XOR-swizzled by (d>>2)&3 so transpose STORES are ~4-way
//   Vs  [ 64][68] key-major  -> vb contiguous across tx     => conflict-free
//   Ps  [128][68] row-major  -> pa addr depends on ty only  => broadcast
// P producers for a row are the 16 same-ty lanes => same warp => __syncwarp.
// ---------------------------------------------------------------------------
__global__ __launch_bounds__(256, 2)
void attn_kernel(const int* __restrict__ masks, float* __restrict__ outp)
{
    extern __shared__ __align__(16) float sm[];
    float* Qs  = sm;                            // 128 x 68
    float* KsT = sm + QT * LDS_;                //  64 x 68 (transposed, swizzled)
    float* Vs  = sm + QT * LDS_ + KT * LDS_;    //  64 x 68
    float* Ps  = sm + QT * LDS_ + 2 * KT * LDS_;// 128 x 68

    const int tid = threadIdx.x;
    const int tx  = tid & 15;
    const int ty  = tid >> 4;
    const int q0  = blockIdx.x * QT;
    const int h   = blockIdx.y;
    const int b   = blockIdx.z;
    const int r0  = ty * 8;
    const int c0  = tx * 4;

    const size_t base = (size_t)b * S_LEN * DMODEL + (size_t)h * HD;

    // Load Q tile (128x64), fold in 1/sqrt(64) = 0.125
    #pragma unroll
    for (int t = 0; t < 8; t++) {
        int idx = tid + t * 256;
        int r = idx >> 4, d4 = idx & 15;
        float4 v = *(const float4*)(gQ + base + (size_t)(q0 + r) * DMODEL + d4 * 4);
        v.x *= 0.125f; v.y *= 0.125f; v.z *= 0.125f; v.w *= 0.125f;
        *(float4*)&Qs[r * LDS_ + d4 * 4] = v;
    }

    // Pack row-mask bits for my 8 rows
    unsigned mrow = 0;
    #pragma unroll
    for (int i = 0; i < 8; i++)
        mrow |= (masks[b * S_LEN + q0 + r0 + i] ? 1u : 0u) << i;

    float m_run[8], l_run[8], acc[8][4];
    #pragma unroll
    for (int i = 0; i < 8; i++) {
        m_run[i] = -3.0e38f;
        l_run[i] = 0.f;
        #pragma unroll
        for (int j = 0; j < 4; j++) acc[i][j] = 0.f;
    }

    for (int k0 = 0; k0 < S_LEN; k0 += KT) {
        __syncthreads();  // all warps done with KsT/Vs/Ps from prior tile

        // Load K (transposed + swizzled) and V (row-major): 64x64 each
        #pragma unroll
        for (int t = 0; t < 4; t++) {
            int idx = tid + t * 256;
            int key = idx >> 4;          // 0..63
            int d4  = idx & 15;          // 0..15 (group of 4 d's)
            size_t g = base + (size_t)(k0 + key) * DMODEL + d4 * 4;
            float4 kv = *(const float4*)(gK + g);
            int kc = (((key >> 2) ^ (d4 & 3)) << 2) | (key & 3);  // swizzled col
            KsT[(d4 * 4 + 0) * LDS_ + kc] = kv.x;
            KsT[(d4 * 4 + 1) * LDS_ + kc] = kv.y;
            KsT[(d4 * 4 + 2) * LDS_ + kc] = kv.z;
            KsT[(d4 * 4 + 3) * LDS_ + kc] = kv.w;
            float4 vv = *(const float4*)(gV + g);
            *(float4*)&Vs[key * LDS_ + d4 * 4] = vv;
        }
        __syncthreads();

        unsigned mcol = 0;
        #pragma unroll
        for (int j = 0; j < 4; j++)
            mcol |= (masks[b * S_LEN + k0 + c0 + j] ? 1u : 0u) << j;

        // S = Q . K^T  (8x4 per thread)
        float s[8][4];
        #pragma unroll
        for (int i = 0; i < 8; i++)
            #pragma unroll
            for (int j = 0; j < 4; j++) s[i][j] = 0.f;

        #pragma unroll 4
        for (int kk = 0; kk < HD; kk += 4) {
            const int swz = ((tx ^ ((kk >> 2) & 3)) << 2);
            float4 kb0 = *(float4*)&KsT[(kk + 0) * LDS_ + swz];
            float4 kb1 = *(float4*)&KsT[(kk + 1) * LDS_ + swz];
            float4 kb2 = *(float4*)&KsT[(kk + 2) * LDS_ + swz];
            float4 kb3 = *(float4*)&KsT[(kk + 3) * LDS_ + swz];
            #pragma unroll
            for (int i = 0; i < 8; i++) {
                float4 qa = *(float4*)&Qs[(r0 + i) * LDS_ + kk];
                s[i][0] = fmaf(qa.x, kb0.x, s[i][0]);
                s[i][0] = fmaf(qa.y, kb1.x, s[i][0]);
                s[i][0] = fmaf(qa.z, kb2.x, s[i][0]);
                s[i][0] = fmaf(qa.w, kb3.x, s[i][0]);
                s[i][1] = fmaf(qa.x, kb0.y, s[i][1]);
                s[i][1] = fmaf(qa.y, kb1.y, s[i][1]);
                s[i][1] = fmaf(qa.z, kb2.y, s[i][1]);
                s[i][1] = fmaf(qa.w, kb3.y, s[i][1]);
                s[i][2] = fmaf(qa.x, kb0.z, s[i][2]);
                s[i][2] = fmaf(qa.y, kb1.z, s[i][2]);
                s[i][2] = fmaf(qa.z, kb2.z, s[i][2]);
                s[i][2] = fmaf(qa.w, kb3.z, s[i][2]);
                s[i][3] = fmaf(qa.x, kb0.w, s[i][3]);
                s[i][3] = fmaf(qa.y, kb1.w, s[i][3]);
                s[i][3] = fmaf(qa.z, kb2.w, s[i][3]);
                s[i][3] = fmaf(qa.w, kb3.w, s[i][3]);
            }
        }

        // Mask: -1e31 absorbs the finite score, matching reference fp32 exactly
        #pragma unroll
        for (int i = 0; i < 8; i++)
            #pragma unroll
            for (int j = 0; j < 4; j++)
                if (!((mrow >> i) & (mcol >> j) & 1u)) s[i][j] = -1e31f;

        // Row max over 64 keys: local 4, butterfly across the 16 tx lanes
        float rmax[8];
        #pragma unroll
        for (int i = 0; i < 8; i++)
            rmax[i] = fmaxf(fmaxf(s[i][0], s[i][1]), fmaxf(s[i][2], s[i][3]));
        #pragma unroll
        for (int msk = 1; msk < 16; msk <<= 1)
            #pragma unroll
            for (int i = 0; i < 8; i++)
                rmax[i] = fmaxf(rmax[i], __shfl_xor_sync(0xffffffffu, rmax[i], msk));

        float rsum[8], scl[8];
        #pragma unroll
        for (int i = 0; i < 8; i++) {
            float mn = fmaxf(m_run[i], rmax[i]);
            scl[i]   = __expf(m_run[i] - mn);
            m_run[i] = mn;
            float sr = 0.f;
            #pragma unroll
            for (int j = 0; j < 4; j++) {
                s[i][j] = __expf(s[i][j] - mn);  // s becomes p in place
                sr += s[i][j];
            }
            rsum[i] = sr;
        }
        #pragma unroll
        for (int msk = 1; msk < 16; msk <<= 1)
            #pragma unroll
            for (int i = 0; i < 8; i++)
                rsum[i] += __shfl_xor_sync(0xffffffffu, rsum[i], msk);
        #pragma unroll
        for (int i = 0; i < 8; i++) {
            l_run[i] = l_run[i] * scl[i] + rsum[i];
            #pragma unroll
            for (int j = 0; j < 4; j++) acc[i][j] *= scl[i];
        }

        // Store P. Producers of row r0+i are the 16 same-ty lanes = same warp,
        // so a warp-level sync suffices before PV reads them back.
        #pragma unroll
        for (int i = 0; i < 8; i++)
            *(float4*)&Ps[(r0 + i) * LDS_ + c0] =
                make_float4(s[i][0], s[i][1], s[i][2], s[i][3]);
        __syncwarp();

        // acc += P . V   (tx now indexes hd columns c0..c0+3)
        #pragma unroll 4
        for (int kk = 0; kk < KT; kk += 4) {
            float4 vb0 = *(float4*)&Vs[(kk + 0) * LDS_ + c0];
            float4 vb1 = *(float4*)&Vs[(kk + 1) * LDS_ + c0];
            float4 vb2 = *(float4*)&Vs[(kk + 2) * LDS_ + c0];
            float4 vb3 = *(float4*)&Vs[(kk + 3) * LDS_ + c0];
            #pragma unroll
            for (int i = 0; i < 8; i++) {
                float4 pa = *(float4*)&Ps[(r0 + i) * LDS_ + kk];
                acc[i][0] = fmaf(pa.x, vb0.x, acc[i][0]);
                acc[i][0] = fmaf(pa.y, vb1.x, acc[i][0]);
                acc[i][0] = fmaf(pa.z, vb2.x, acc[i][0]);
                acc[i][0] = fmaf(pa.w, vb3.x, acc[i][0]);
                acc[i][1] = fmaf(pa.x, vb0.y, acc[i][1]);
                acc[i][1] = fmaf(pa.y, vb1.y, acc[i][1]);
                acc[i][1] = fmaf(pa.z, vb2.y, acc[i][1]);
                acc[i][1] = fmaf(pa.w, vb3.y, acc[i][1]);
                acc[i][2] = fmaf(pa.x, vb0.z, acc[i][2]);
                acc[i][2] = fmaf(pa.y, vb1.z, acc[i][2]);
                acc[i][2] = fmaf(pa.z, vb2.z, acc[i][2]);
                acc[i][2] = fmaf(pa.w, vb3.z, acc[i][2]);
                acc[i][3] = fmaf(pa.x, vb0.w, acc[i][3]);
                acc[i][3] = fmaf(pa.y, vb1.w, acc[i][3]);
                acc[i][3] = fmaf(pa.z, vb2.w, acc[i][3]);
                acc[i][3] = fmaf(pa.w, vb3.w, acc[i][3]);
            }
        }
    }

    // Epilogue: ctx = acc / l, write [b, s, h*64 + d]
    #pragma unroll
    for (int i = 0; i < 8; i++) {
        float inv = 1.0f / l_run[i];
        float4 r;
        r.x = acc[i][0] * inv;
        r.y = acc[i][1] * inv;
        r.z = acc[i][2] * inv;
        r.w = acc[i][3] * inv;
        *(float4*)(outp + (size_t)(b * S_LEN + q0 + r0 + i) * DMODEL + h * HD + c0) = r;
    }
}

// ---------------------------------------------------------------------------
extern "C" void kernel_launch(void* const* d_in, const int* in_sizes, int n_in,
                              void* d_out, int out_size)
{
    (void)in_sizes; (void)n_in; (void)out_size;
    const float* toks  = (const float*)d_in[0];
    const int*   masks = (const int*)  d_in[1];
    const float* Wq    = (const float*)d_in[2];
    const float* bq    = (const float*)d_in[3];
    const float* Wk    = (const float*)d_in[4];
    const float* bk    = (const float*)d_in[5];
    const float* Wv    = (const float*)d_in[6];
    const float* bv    = (const float*)d_in[7];
    float* outp = (float*)d_out;

    // Qs + KsT + Vs + Ps = (128 + 64 + 64 + 128) * 68 * 4 = 104448 bytes
    const int smem_bytes = (QT + KT + KT + QT) * LDS_ * (int)sizeof(float);
    cudaFuncSetAttribute(attn_kernel,
                         cudaFuncAttributeMaxDynamicSharedMemorySize, smem_bytes);

    qkv_gemm_kernel<<<dim3(64, 12, 3), 256>>>(toks, Wq, bq, Wk, bk, Wv, bv);
    attn_kernel<<<dim3(S_LEN / QT, NHEADS, 4), 256, smem_bytes>>>(masks, outp);
}

// round 11
// speedup vs baseline: 1.6857x; 1.1210x over previous
#include <cuda_runtime.h>

#define S_LEN  2048
#define NHEADS 12
#define DMODEL 768
#define HD     64
#define MTOT   8192  // B * S

#define QT  128   // q rows per CTA
#define KT  64    // keys per tile
#define LDS_ 68   // padded stride for 64-wide tiles (floats)
#define LDQ  132  // padded stride for 128-wide tiles (floats)

typedef unsigned long long u64;

// ---- packed fp32x2 helpers (sm_103a dual-issue fp32 path) --------------------
__device__ __forceinline__ u64 ffma2(u64 a, u64 b, u64 c) {
    u64 d;
    asm("fma.rn.f32x2 %0, %1, %2, %3;" : "=l"(d) : "l"(a), "l"(b), "l"(c));
    return d;
}
__device__ __forceinline__ u64 fmul2(u64 a, u64 b) {
    u64 d;
    asm("mul.rn.f32x2 %0, %1, %2;" : "=l"(d) : "l"(a), "l"(b));
    return d;
}
__device__ __forceinline__ u64 pk2(float x, float y) {
    u64 d;
    asm("mov.b64 %0, {%1, %2};" : "=l"(d)
        : "r"(__float_as_uint(x)), "r"(__float_as_uint(y)));
    return d;
}
__device__ __forceinline__ u64 pk1(float x) { return pk2(x, x); }
__device__ __forceinline__ float2 up2(u64 v) {
    unsigned lo, hi;
    asm("mov.b64 {%0, %1}, %2;" : "=r"(lo), "=r"(hi) : "l"(v));
    return make_float2(__uint_as_float(lo), __uint_as_float(hi));
}

// Scratch for Q, K, V projections (allocation-free rule: __device__ globals)
__device__ float gQ[(size_t)MTOT * DMODEL];
__device__ float gK[(size_t)MTOT * DMODEL];
__device__ float gV[(size_t)MTOT * DMODEL];

// ---------------------------------------------------------------------------
// Fused QKV projection: out[z] = toks @ W[z] + b[z]   (FFMA2 mainloop)
// M=8192, N=768, K=768. Block 128x64, BK=16, 256 thr, 8x4/thread (4 row-pairs).
// ---------------------------------------------------------------------------
__global__ __launch_bounds__(256)
void qkv_gemm_kernel(const float* __restrict__ toks,
                     const float* __restrict__ Wq, const float* __restrict__ bq,
                     const float* __restrict__ Wk, const float* __restrict__ bk,
                     const float* __restrict__ Wv, const float* __restrict__ bv)
{
    const int z = blockIdx.z;
    const float* __restrict__ W    = (z == 0) ? Wq : (z == 1) ? Wk : Wv;
    const float* __restrict__ bias = (z == 0) ? bq : (z == 1) ? bk : bv;
    float* __restrict__ outp       = (z == 0) ? gQ : (z == 1) ? gK : gV;

    const int m0  = blockIdx.x * 128;
    const int n0  = blockIdx.y * 64;
    const int tid = threadIdx.x;
    const int tx  = tid & 15;
    const int ty  = tid >> 4;

    __shared__ __align__(16) float As[16][132];  // [k][m] transposed
    __shared__ __align__(16) float Bs[16][64];   // [k][n]

    u64 accp[4][4];  // row-pairs (2p,2p+1) x 4 n-cols
    #pragma unroll
    for (int p = 0; p < 4; p++)
        #pragma unroll
        for (int j = 0; j < 4; j++) accp[p][j] = 0ull;

    for (int k0 = 0; k0 < DMODEL; k0 += 16) {
        #pragma unroll
        for (int it = 0; it < 2; it++) {
            int idx = tid + it * 256;
            int row = idx >> 2;
            int c4  = idx & 3;
            float4 v = *(const float4*)(toks + (size_t)(m0 + row) * DMODEL + k0 + c4 * 4);
            As[c4 * 4 + 0][row] = v.x;
            As[c4 * 4 + 1][row] = v.y;
            As[c4 * 4 + 2][row] = v.z;
            As[c4 * 4 + 3][row] = v.w;
        }
        {
            int row = tid >> 4;
            int c4  = tid & 15;
            *(float4*)&Bs[row][c4 * 4] =
                *(const float4*)(W + (size_t)(k0 + row) * DMODEL + n0 + c4 * 4);
        }
        __syncthreads();

        #pragma unroll
        for (int kk = 0; kk < 16; kk++) {
            float4 b4 = *(float4*)&Bs[kk][tx * 4];
            u64 bp[4] = {pk1(b4.x), pk1(b4.y), pk1(b4.z), pk1(b4.w)};
            ulonglong2 a01 = *(ulonglong2*)&As[kk][ty * 8];
            ulonglong2 a23 = *(ulonglong2*)&As[kk][ty * 8 + 4];
            u64 ap[4] = {a01.x, a01.y, a23.x, a23.y};
            #pragma unroll
            for (int p = 0; p < 4; p++)
                #pragma unroll
                for (int j = 0; j < 4; j++)
                    accp[p][j] = ffma2(ap[p], bp[j], accp[p][j]);
        }
        __syncthreads();
    }

    float4 b4 = *(const float4*)(bias + n0 + tx * 4);
    #pragma unroll
    for (int p = 0; p < 4; p++) {
        float2 c0v = up2(accp[p][0]);
        float2 c1v = up2(accp[p][1]);
        float2 c2v = up2(accp[p][2]);
        float2 c3v = up2(accp[p][3]);
        float4 rlo = make_float4(c0v.x + b4.x, c1v.x + b4.y, c2v.x + b4.z, c3v.x + b4.w);
        float4 rhi = make_float4(c0v.y + b4.x, c1v.y + b4.y, c2v.y + b4.z, c3v.y + b4.w);
        *(float4*)(outp + (size_t)(m0 + ty * 8 + 2 * p + 0) * DMODEL + n0 + tx * 4) = rlo;
        *(float4*)(outp + (size_t)(m0 + ty * 8 + 2 * p + 1) * DMODEL + n0 + tx * 4) = rhi;
    }
}

// ---------------------------------------------------------------------------
// Flash attention, fp32 with FFMA2. CTA = (b, h, 128-row q tile), 64-key tiles.
// 256 threads as 16x16: ty owns 8 q-rows (4 packed row-pairs), tx owns 4 keys
// (QK) / 4 hd-cols (PV).
//
// smem layouts (all mainloop reads conflict-free / broadcast):
//   QsT [64 d][128 rows +pad] : row-pairs load as u64; address tx-independent
//   KsT [64 d][ 64 keys+pad]  : XOR-swizzled (as before); contiguous across tx
//   Vs  [64 key][64 d +pad]   : contiguous across tx
//   PsT [64 key][128 rows+pad]: packed row-pair u64 stores, row-group XOR
//                               swizzle by (key>>2)&7 (~2-way store conflicts);
//                               reads are tx-independent broadcasts
// ---------------------------------------------------------------------------
__global__ __launch_bounds__(256, 2)
void attn_kernel(const int* __restrict__ masks, float* __restrict__ outp)
{
    extern __shared__ __align__(16) float sm[];
    float* QsT = sm;                    // 64 x 132
    float* KsT = sm + 64 * LDQ;         // 64 x 68
    float* Vs  = KsT + KT * LDS_;       // 64 x 68
    float* PsT = Vs + KT * LDS_;        // 64 x 132

    const int tid = threadIdx.x;
    const int tx  = tid & 15;
    const int ty  = tid >> 4;
    const int q0  = blockIdx.x * QT;
    const int h   = blockIdx.y;
    const int b   = blockIdx.z;
    const int r0  = ty * 8;
    const int c0  = tx * 4;

    const size_t base = (size_t)b * S_LEN * DMODEL + (size_t)h * HD;

    // Load Q tile (128x64) transposed into QsT, folding in 1/sqrt(64) = 0.125
    #pragma unroll
    for (int t = 0; t < 8; t++) {
        int idx = tid + t * 256;
        int r = idx >> 4, d4 = idx & 15;
        float4 v = *(const float4*)(gQ + base + (size_t)(q0 + r) * DMODEL + d4 * 4);
        QsT[(d4 * 4 + 0) * LDQ + r] = v.x * 0.125f;
        QsT[(d4 * 4 + 1) * LDQ + r] = v.y * 0.125f;
        QsT[(d4 * 4 + 2) * LDQ + r] = v.z * 0.125f;
        QsT[(d4 * 4 + 3) * LDQ + r] = v.w * 0.125f;
    }

    // Row-mask bits for my 8 rows (bit i <-> row r0+i)
    unsigned mrow = 0;
    #pragma unroll
    for (int i = 0; i < 8; i++)
        mrow |= (masks[b * S_LEN + q0 + r0 + i] ? 1u : 0u) << i;

    float m_run[8], l_run[8];
    u64 accp[4][4];  // row-pairs x 4 hd-cols
    #pragma unroll
    for (int i = 0; i < 8; i++) { m_run[i] = -3.0e38f; l_run[i] = 0.f; }
    #pragma unroll
    for (int p = 0; p < 4; p++)
        #pragma unroll
        for (int j = 0; j < 4; j++) accp[p][j] = 0ull;

    for (int k0 = 0; k0 < S_LEN; k0 += KT) {
        __syncthreads();  // prior tile done with KsT/Vs/PsT

        // Load K (transposed + swizzled) and V (row-major): 64x64 each
        #pragma unroll
        for (int t = 0; t < 4; t++) {
            int idx = tid + t * 256;
            int key = idx >> 4;
            int d4  = idx & 15;
            size_t g = base + (size_t)(k0 + key) * DMODEL + d4 * 4;
            float4 kv = *(const float4*)(gK + g);
            int kc = (((key >> 2) ^ (d4 & 3)) << 2) | (key & 3);
            KsT[(d4 * 4 + 0) * LDS_ + kc] = kv.x;
            KsT[(d4 * 4 + 1) * LDS_ + kc] = kv.y;
            KsT[(d4 * 4 + 2) * LDS_ + kc] = kv.z;
            KsT[(d4 * 4 + 3) * LDS_ + kc] = kv.w;
            float4 vv = *(const float4*)(gV + g);
            *(float4*)&Vs[key * LDS_ + d4 * 4] = vv;
        }
        __syncthreads();

        unsigned mcol = 0;
        #pragma unroll
        for (int j = 0; j < 4; j++)
            mcol |= (masks[b * S_LEN + k0 + c0 + j] ? 1u : 0u) << j;

        // ---- S = Q.K^T : packed row-pairs x 4 keys --------------------------
        u64 sp[4][4];
        #pragma unroll
        for (int p = 0; p < 4; p++)
            #pragma unroll
            for (int j = 0; j < 4; j++) sp[p][j] = 0ull;

        #pragma unroll 4
        for (int kk = 0; kk < HD; kk += 4) {
            const int swz = ((tx ^ ((kk >> 2) & 3)) << 2);
            #pragma unroll
            for (int d = 0; d < 4; d++) {
                float4 kb = *(float4*)&KsT[(kk + d) * LDS_ + swz];
                u64 kp0 = pk1(kb.x), kp1 = pk1(kb.y), kp2 = pk1(kb.z), kp3 = pk1(kb.w);
                ulonglong2 qa = *(ulonglong2*)&QsT[(kk + d) * LDQ + r0];
                ulonglong2 qb = *(ulonglong2*)&QsT[(kk + d) * LDQ + r0 + 4];
                u64 qp[4] = {qa.x, qa.y, qb.x, qb.y};
                #pragma unroll
                for (int p = 0; p < 4; p++) {
                    sp[p][0] = ffma2(qp[p], kp0, sp[p][0]);
                    sp[p][1] = ffma2(qp[p], kp1, sp[p][1]);
                    sp[p][2] = ffma2(qp[p], kp2, sp[p][2]);
                    sp[p][3] = ffma2(qp[p], kp3, sp[p][3]);
                }
            }
        }

        // ---- softmax (scalar): unpack, mask, online max/sum ----------------
        float sx[8][4];
        #pragma unroll
        for (int p = 0; p < 4; p++)
            #pragma unroll
            for (int j = 0; j < 4; j++) {
                float2 t = up2(sp[p][j]);
                sx[2 * p + 0][j] = t.x;
                sx[2 * p + 1][j] = t.y;
            }

        // Mask: -1e31 absorbs the finite score, matching reference fp32 exactly
        #pragma unroll
        for (int i = 0; i < 8; i++)
            #pragma unroll
            for (int j = 0; j < 4; j++)
                if (!((mrow >> i) & (mcol >> j) & 1u)) sx[i][j] = -1e31f;

        float rmax[8];
        #pragma unroll
        for (int i = 0; i < 8; i++)
            rmax[i] = fmaxf(fmaxf(sx[i][0], sx[i][1]), fmaxf(sx[i][2], sx[i][3]));
        #pragma unroll
        for (int msk = 1; msk < 16; msk <<= 1)
            #pragma unroll
            for (int i = 0; i < 8; i++)
                rmax[i] = fmaxf(rmax[i], __shfl_xor_sync(0xffffffffu, rmax[i], msk));

        float rsum[8], scl[8];
        #pragma unroll
        for (int i = 0; i < 8; i++) {
            float mn = fmaxf(m_run[i], rmax[i]);
            scl[i]   = __expf(m_run[i] - mn);
            m_run[i] = mn;
            float sr = 0.f;
            #pragma unroll
            for (int j = 0; j < 4; j++) {
                sx[i][j] = __expf(sx[i][j] - mn);
                sr += sx[i][j];
            }
            rsum[i] = sr;
        }
        #pragma unroll
        for (int msk = 1; msk < 16; msk <<= 1)
            #pragma unroll
            for (int i = 0; i < 8; i++)
                rsum[i] += __shfl_xor_sync(0xffffffffu, rsum[i], msk);
        #pragma unroll
        for (int i = 0; i < 8; i++)
            l_run[i] = l_run[i] * scl[i] + rsum[i];
        #pragma unroll
        for (int p = 0; p < 4; p++) {
            u64 sc = pk2(scl[2 * p], scl[2 * p + 1]);
            #pragma unroll
            for (int j = 0; j < 4; j++) accp[p][j] = fmul2(accp[p][j], sc);
        }

        // ---- store P transposed as packed row-pairs (swizzled) -------------
        // Producers of rows r0..r0+7 are the 16 same-ty lanes = same warp.
        #pragma unroll
        for (int j = 0; j < 4; j++) {
            const int key = c0 + j;
            #pragma unroll
            for (int p = 0; p < 4; p++) {
                int g   = (2 * ty + (p >> 1)) ^ (tx & 7);
                int col = (g << 2) | ((p & 1) * 2);
                *(u64*)&PsT[key * LDQ + col] = pk2(sx[2 * p][j], sx[2 * p + 1][j]);
            }
        }
        __syncwarp();

        // ---- acc += P.V : packed row-pairs x 4 hd-cols ----------------------
        #pragma unroll 4
        for (int kk = 0; kk < KT; kk += 4) {
            const int swl = (kk >> 2) & 7;
            #pragma unroll
            for (int l = 0; l < 4; l++) {
                float4 vb = *(float4*)&Vs[(kk + l) * LDS_ + c0];
                u64 vp0 = pk1(vb.x), vp1 = pk1(vb.y), vp2 = pk1(vb.z), vp3 = pk1(vb.w);
                int g0 = ((2 * ty + 0) ^ swl) << 2;
                int g1 = ((2 * ty + 1) ^ swl) << 2;
                ulonglong2 pa = *(ulonglong2*)&PsT[(kk + l) * LDQ + g0];
                ulonglong2 pb = *(ulonglong2*)&PsT[(kk + l) * LDQ + g1];
                u64 pp[4] = {pa.x, pa.y, pb.x, pb.y};
                #pragma unroll
                for (int p = 0; p < 4; p++) {
                    accp[p][0] = ffma2(pp[p], vp0, accp[p][0]);
                    accp[p][1] = ffma2(pp[p], vp1, accp[p][1]);
                    accp[p][2] = ffma2(pp[p], vp2, accp[p][2]);
                    accp[p][3] = ffma2(pp[p], vp3, accp[p][3]);
                }
            }
        }
    }

    // Epilogue: ctx = acc / l, write [b, s, h*64 + d]
    #pragma unroll
    for (int p = 0; p < 4; p++) {
        float2 a0 = up2(accp[p][0]);
        float2 a1 = up2(accp[p][1]);
        float2 a2 = up2(accp[p][2]);
        float2 a3 = up2(accp[p][3]);
        float inv0 = 1.0f / l_run[2 * p + 0];
        float inv1 = 1.0f / l_run[2 * p + 1];
        float4 rlo = make_float4(a0.x * inv0, a1.x * inv0, a2.x * inv0, a3.x * inv0);
        float4 rhi = make_float4(a0.y * inv1, a1.y * inv1, a2.y * inv1, a3.y * inv1);
        *(float4*)(outp + (size_t)(b * S_LEN + q0 + r0 + 2 * p + 0) * DMODEL + h * HD + c0) = rlo;
        *(float4*)(outp + (size_t)(b * S_LEN + q0 + r0 + 2 * p + 1) * DMODEL + h * HD + c0) = rhi;
    }
}

// ---------------------------------------------------------------------------
extern "C" void kernel_launch(void* const* d_in, const int* in_sizes, int n_in,
                              void* d_out, int out_size)
{
    (void)in_sizes; (void)n_in; (void)out_size;
    const float* toks  = (const float*)d_in[0];
    const int*   masks = (const int*)  d_in[1];
    const float* Wq    = (const float*)d_in[2];
    const float* bq    = (const float*)d_in[3];
    const float* Wk    = (const float*)d_in[4];
    const float* bk    = (const float*)d_in[5];
    const float* Wv    = (const float*)d_in[6];
    const float* bv    = (const float*)d_in[7];
    float* outp = (float*)d_out;

    // QsT(64x132) + KsT(64x68) + Vs(64x68) + PsT(64x132) = 25600 floats
    const int smem_bytes = (64 * LDQ + KT * LDS_ + KT * LDS_ + 64 * LDQ) * (int)sizeof(float);
    cudaFuncSetAttribute(attn_kernel,
                         cudaFuncAttributeMaxDynamicSharedMemorySize, smem_bytes);

    qkv_gemm_kernel<<<dim3(64, 12, 3), 256>>>(toks, Wq, bq, Wk, bk, Wv, bv);
    attn_kernel<<<dim3(S_LEN / QT, NHEADS, 4), 256, smem_bytes>>>(masks, outp);
}

// round 17
// speedup vs baseline: 2.0806x; 1.2342x over previous
#include <cuda_runtime.h>
#include <cuda_bf16.h>
#include <cstdint>

#define S_LEN  2048
#define NHEADS 12
#define DMODEL 768
#define HD     64
#define MTOT   8192  // B * S

#define QT  128   // q rows per CTA (attn)
#define KT  64    // keys per tile (attn)
#define LDS_ 68   // padded stride for 64-wide tiles (floats)
#define LDQ  132  // padded stride for 128-wide tiles (floats)

typedef unsigned long long u64;

// ============================ small helpers =================================
__device__ __forceinline__ uint32_t smem_u32(const void* p) {
    uint32_t a;
    asm("{ .reg .u64 t; cvta.to.shared.u64 t, %1; cvt.u32.u64 %0, t; }"
        : "=r"(a) : "l"(p));
    return a;
}
__device__ __forceinline__ u64 ffma2(u64 a, u64 b, u64 c) {
    u64 d;
    asm("fma.rn.f32x2 %0, %1, %2, %3;" : "=l"(d) : "l"(a), "l"(b), "l"(c));
    return d;
}
__device__ __forceinline__ u64 fmul2(u64 a, u64 b) {
    u64 d;
    asm("mul.rn.f32x2 %0, %1, %2;" : "=l"(d) : "l"(a), "l"(b));
    return d;
}
__device__ __forceinline__ u64 pk2(float x, float y) {
    u64 d;
    asm("mov.b64 %0, {%1, %2};" : "=l"(d)
        : "r"(__float_as_uint(x)), "r"(__float_as_uint(y)));
    return d;
}
__device__ __forceinline__ u64 pk1(float x) { return pk2(x, x); }
__device__ __forceinline__ float2 up2(u64 v) {
    unsigned lo, hi;
    asm("mov.b64 {%0, %1}, %2;" : "=r"(lo), "=r"(hi) : "l"(v));
    return make_float2(__uint_as_float(lo), __uint_as_float(hi));
}

// ---- arch-agnostic tensor-core primitives (compile at compute_103) ---------
__device__ __forceinline__ void ldsm_x4(uint32_t& r0, uint32_t& r1,
                                        uint32_t& r2, uint32_t& r3, uint32_t addr) {
    asm volatile("ldmatrix.sync.aligned.m8n8.x4.shared.b16 {%0,%1,%2,%3}, [%4];"
                 : "=r"(r0), "=r"(r1), "=r"(r2), "=r"(r3) : "r"(addr));
}
__device__ __forceinline__ void ldsm_x2(uint32_t& r0, uint32_t& r1, uint32_t addr) {
    asm volatile("ldmatrix.sync.aligned.m8n8.x2.shared.b16 {%0,%1}, [%2];"
                 : "=r"(r0), "=r"(r1) : "r"(addr));
}
__device__ __forceinline__ void mma_bf16(float* d, const uint32_t* a, const uint32_t* b) {
    asm volatile(
        "mma.sync.aligned.m16n8k16.row.col.f32.bf16.bf16.f32 "
        "{%0,%1,%2,%3}, {%4,%5,%6,%7}, {%8,%9}, {%0,%1,%2,%3};"
        : "+f"(d[0]), "+f"(d[1]), "+f"(d[2]), "+f"(d[3])
        : "r"(a[0]), "r"(a[1]), "r"(a[2]), "r"(a[3]), "r"(b[0]), "r"(b[1]));
}
__device__ __forceinline__ void cp_async16(uint32_t smem_addr, const void* gptr) {
    asm volatile("cp.async.ca.shared.global [%0], [%1], 16;"
                 :: "r"(smem_addr), "l"(gptr));
}
#define CP_COMMIT() asm volatile("cp.async.commit_group;" ::: "memory")
#define CP_WAIT0()  asm volatile("cp.async.wait_group 0;" ::: "memory")

// ============================ device scratch ================================
__device__ float gQ[(size_t)MTOT * DMODEL];
__device__ float gK[(size_t)MTOT * DMODEL];
__device__ float gV[(size_t)MTOT * DMODEL];
__device__ __nv_bfloat16 tokHi[(size_t)MTOT * DMODEL];
__device__ __nv_bfloat16 tokLo[(size_t)MTOT * DMODEL];
__device__ __nv_bfloat16 wtHi[(size_t)3 * DMODEL * DMODEL];  // W^T: [z][n][k]
__device__ __nv_bfloat16 wtLo[(size_t)3 * DMODEL * DMODEL];

// ============================ prep kernels ==================================
__device__ __forceinline__ void split1(float x, __nv_bfloat16& h, __nv_bfloat16& l) {
    h = __float2bfloat16(x);
    l = __float2bfloat16(x - __bfloat162float(h));
}

__global__ __launch_bounds__(256)
void split_toks_kernel(const float* __restrict__ toks)
{
    size_t i = ((size_t)blockIdx.x * 256 + threadIdx.x) * 4;
    float4 v = *(const float4*)(toks + i);
    __nv_bfloat16 h[4], l[4];
    split1(v.x, h[0], l[0]); split1(v.y, h[1], l[1]);
    split1(v.z, h[2], l[2]); split1(v.w, h[3], l[3]);
    __nv_bfloat162 h01(h[0], h[1]), h23(h[2], h[3]);
    __nv_bfloat162 l01(l[0], l[1]), l23(l[2], l[3]);
    *(__nv_bfloat162*)(tokHi + i)     = h01;
    *(__nv_bfloat162*)(tokHi + i + 2) = h23;
    *(__nv_bfloat162*)(tokLo + i)     = l01;
    *(__nv_bfloat162*)(tokLo + i + 2) = l23;
}

__global__ __launch_bounds__(256)
void transpose_split_w_kernel(const float* __restrict__ Wq,
                              const float* __restrict__ Wk,
                              const float* __restrict__ Wv)
{
    const int z = blockIdx.z;
    const float* __restrict__ W = (z == 0) ? Wq : (z == 1) ? Wk : Wv;
    __shared__ float tile[32][33];
    const int k0 = blockIdx.x * 32, n0 = blockIdx.y * 32;
    const int tx = threadIdx.x, ty = threadIdx.y;  // 32 x 8
    #pragma unroll
    for (int j = 0; j < 4; j++)
        tile[ty + 8 * j][tx] = W[(size_t)(k0 + ty + 8 * j) * DMODEL + n0 + tx];
    __syncthreads();
    const size_t zoff = (size_t)z * DMODEL * DMODEL;
    #pragma unroll
    for (int j = 0; j < 4; j++) {
        int n = n0 + ty + 8 * j, k = k0 + tx;
        __nv_bfloat16 h, l;
        split1(tile[tx][ty + 8 * j], h, l);
        wtHi[zoff + (size_t)n * DMODEL + k] = h;
        wtLo[zoff + (size_t)n * DMODEL + k] = l;
    }
}

// ============================ mma.sync QKV GEMM =============================
// C[z] = toks @ W[z] + b[z], bf16 2-term split (hi*hi + hi*lo + lo*hi).
// CTA 128x128, 8 warps (2m x 4n), warp tile 64x32 = 4x4 m16n8k16 fragments.
// K-chunks of 32, double-buffered via cp.async.
// smem row stride = 80B (40 bf16): rows 0..7 hit mod-128 offsets
// {0,80,32,112,64,16,96,48} -> ldmatrix phases conflict-free.
#define KC       32
#define NCHUNK   (DMODEL / KC)          // 24
#define TROW_B   80                     // bytes per smem tile row
#define TILE_B   (128 * TROW_B)         // 10240 B per operand tile
#define STAGE_B  (4 * TILE_B)           // AH, AL, BH, BL
#define GSMEM_B  (2 * STAGE_B)          // 81920 B

__global__ __launch_bounds__(256)
void qkv_mma_kernel(const float* __restrict__ bq,
                    const float* __restrict__ bk,
                    const float* __restrict__ bv)
{
    extern __shared__ __align__(128) char gsm[];
    const uint32_t sbase = smem_u32(gsm);
    const int tid  = threadIdx.x, wid = tid >> 5, lane = tid & 31;
    const int m0 = blockIdx.x * 128, n0 = blockIdx.y * 128, z = blockIdx.z;
    const int mwarp = (wid & 1) * 64, nwarp = (wid >> 1) * 32;

    const size_t zoff = (size_t)z * DMODEL * DMODEL;
    const __nv_bfloat16* __restrict__ srcs[4] = {
        tokHi + (size_t)m0 * DMODEL, tokLo + (size_t)m0 * DMODEL,
        wtHi + zoff + (size_t)n0 * DMODEL, wtLo + zoff + (size_t)n0 * DMODEL };

    float acc[4][4][4];
    #pragma unroll
    for (int mi = 0; mi < 4; mi++)
        #pragma unroll
        for (int nj = 0; nj < 4; nj++)
            #pragma unroll
            for (int r = 0; r < 4; r++) acc[mi][nj][r] = 0.f;

    // per-thread ldmatrix base addresses (byte offsets inside a tile)
    const uint32_t aRowOff = (uint32_t)(mwarp + (lane & 15)) * TROW_B
                           + ((lane >> 4) << 3) * 2;              // +8 bf16 col for hi-lanes
    const uint32_t bRowOff = (uint32_t)(nwarp + (lane & 7)) * TROW_B
                           + (((lane >> 3) & 1) << 3) * 2;
    // NOTE: for ldsm_x2 only lanes 0..15 addresses matter; lanes 16..31 reuse pattern harmlessly.

    // chunk loader: 4 tiles x 512 x 16B via cp.async; each thread 8 transfers
    auto load_chunk = [&](int c, int s) {
        const int kc = c * KC;
        const uint32_t dst0 = sbase + (uint32_t)s * STAGE_B;
        #pragma unroll
        for (int t = 0; t < 4; t++) {
            const __nv_bfloat16* src = srcs[t];
            #pragma unroll
            for (int it = 0; it < 2; it++) {
                int idx = tid + it * 256;      // 0..511
                int row = idx >> 2;            // 0..127
                int j   = idx & 3;             // 16B unit within 64B row-chunk
                cp_async16(dst0 + (uint32_t)t * TILE_B + row * TROW_B + j * 16,
                           src + (size_t)row * DMODEL + kc + j * 8);
            }
        }
        CP_COMMIT();
    };

    load_chunk(0, 0);
    CP_WAIT0();
    __syncthreads();

    for (int c = 0; c < NCHUNK; c++) {
        const int s = c & 1;
        if (c + 1 < NCHUNK) load_chunk(c + 1, 1 - s);

        const uint32_t st = sbase + (uint32_t)s * STAGE_B;
        #pragma unroll
        for (int ks = 0; ks < 2; ks++) {
            const uint32_t kb = ks * 16 * 2;  // byte offset of k-step
            uint32_t ah[4][4], al[4][4], bh[4][2], bl[4][2];
            #pragma unroll
            for (int mi = 0; mi < 4; mi++) {
                uint32_t ra = st + aRowOff + (uint32_t)(mi * 16) * TROW_B + kb;
                ldsm_x4(ah[mi][0], ah[mi][1], ah[mi][2], ah[mi][3], ra);
                ldsm_x4(al[mi][0], al[mi][1], al[mi][2], al[mi][3], ra + TILE_B);
            }
            #pragma unroll
            for (int nj = 0; nj < 4; nj++) {
                uint32_t rb = st + 2 * TILE_B + bRowOff + (uint32_t)(nj * 8) * TROW_B + kb;
                ldsm_x2(bh[nj][0], bh[nj][1], rb);
                ldsm_x2(bl[nj][0], bl[nj][1], rb + TILE_B);
            }
            #pragma unroll
            for (int mi = 0; mi < 4; mi++)
                #pragma unroll
                for (int nj = 0; nj < 4; nj++) {
                    mma_bf16(acc[mi][nj], ah[mi], bh[nj]);
                    mma_bf16(acc[mi][nj], ah[mi], bl[nj]);
                    mma_bf16(acc[mi][nj], al[mi], bh[nj]);
                }
        }

        if (c + 1 < NCHUNK) CP_WAIT0();
        __syncthreads();
    }

    // epilogue: fragment (mi,nj): c0,c1 -> row g, cols tc,tc+1; c2,c3 -> row g+8
    const float* bias = (z == 0) ? bq : (z == 1) ? bk : bv;
    float* outp       = (z == 0) ? gQ : (z == 1) ? gK : gV;
    const int g  = lane >> 2;
    const int tc = (lane & 3) * 2;
    #pragma unroll
    for (int nj = 0; nj < 4; nj++) {
        const int col = n0 + nwarp + nj * 8 + tc;
        float2 bsv = *(const float2*)(bias + col);
        #pragma unroll
        for (int mi = 0; mi < 4; mi++) {
            const int r0 = m0 + mwarp + mi * 16 + g;
            float2 lo = make_float2(acc[mi][nj][0] + bsv.x, acc[mi][nj][1] + bsv.y);
            float2 hi = make_float2(acc[mi][nj][2] + bsv.x, acc[mi][nj][3] + bsv.y);
            *(float2*)(outp + (size_t)r0 * DMODEL + col)       = lo;
            *(float2*)(outp + (size_t)(r0 + 8) * DMODEL + col) = hi;
        }
    }
}

// ---------------------------------------------------------------------------
// Flash attention, fp32 with FFMA2 (unchanged — bit-identical math).
// ---------------------------------------------------------------------------
__global__ __launch_bounds__(256, 2)
void attn_kernel(const int* __restrict__ masks, float* __restrict__ outp)
{
    extern __shared__ __align__(16) float sm[];
    float* QsT = sm;                    // 64 x 132
    float* KsT = sm + 64 * LDQ;         // 64 x 68
    float* Vs  = KsT + KT * LDS_;       // 64 x 68
    float* PsT = Vs + KT * LDS_;        // 64 x 132

    const int tid = threadIdx.x;
    const int tx  = tid & 15;
    const int ty  = tid >> 4;
    const int q0  = blockIdx.x * QT;
    const int h   = blockIdx.y;
    const int b   = blockIdx.z;
    const int r0  = ty * 8;
    const int c0  = tx * 4;

    const size_t base = (size_t)b * S_LEN * DMODEL + (size_t)h * HD;

    #pragma unroll
    for (int t = 0; t < 8; t++) {
        int idx = tid + t * 256;
        int r = idx >> 4, d4 = idx & 15;
        float4 v = *(const float4*)(gQ + base + (size_t)(q0 + r) * DMODEL + d4 * 4);
        QsT[(d4 * 4 + 0) * LDQ + r] = v.x * 0.125f;
        QsT[(d4 * 4 + 1) * LDQ + r] = v.y * 0.125f;
        QsT[(d4 * 4 + 2) * LDQ + r] = v.z * 0.125f;
        QsT[(d4 * 4 + 3) * LDQ + r] = v.w * 0.125f;
    }

    unsigned mrow = 0;
    #pragma unroll
    for (int i = 0; i < 8; i++)
        mrow |= (masks[b * S_LEN + q0 + r0 + i] ? 1u : 0u) << i;

    float m_run[8], l_run[8];
    u64 accp[4][4];
    #pragma unroll
    for (int i = 0; i < 8; i++) { m_run[i] = -3.0e38f; l_run[i] = 0.f; }
    #pragma unroll
    for (int p = 0; p < 4; p++)
        #pragma unroll
        for (int j = 0; j < 4; j++) accp[p][j] = 0ull;

    for (int k0 = 0; k0 < S_LEN; k0 += KT) {
        __syncthreads();

        #pragma unroll
        for (int t = 0; t < 4; t++) {
            int idx = tid + t * 256;
            int key = idx >> 4;
            int d4  = idx & 15;
            size_t g = base + (size_t)(k0 + key) * DMODEL + d4 * 4;
            float4 kv = *(const float4*)(gK + g);
            int kc = (((key >> 2) ^ (d4 & 3)) << 2) | (key & 3);
            KsT[(d4 * 4 + 0) * LDS_ + kc] = kv.x;
            KsT[(d4 * 4 + 1) * LDS_ + kc] = kv.y;
            KsT[(d4 * 4 + 2) * LDS_ + kc] = kv.z;
            KsT[(d4 * 4 + 3) * LDS_ + kc] = kv.w;
            float4 vv = *(const float4*)(gV + g);
            *(float4*)&Vs[key * LDS_ + d4 * 4] = vv;
        }
        __syncthreads();

        unsigned mcol = 0;
        #pragma unroll
        for (int j = 0; j < 4; j++)
            mcol |= (masks[b * S_LEN + k0 + c0 + j] ? 1u : 0u) << j;

        u64 sp[4][4];
        #pragma unroll
        for (int p = 0; p < 4; p++)
            #pragma unroll
            for (int j = 0; j < 4; j++) sp[p][j] = 0ull;

        #pragma unroll 4
        for (int kk = 0; kk < HD; kk += 4) {
            const int swz = ((tx ^ ((kk >> 2) & 3)) << 2);
            #pragma unroll
            for (int d = 0; d < 4; d++) {
                float4 kb = *(float4*)&KsT[(kk + d) * LDS_ + swz];
                u64 kp0 = pk1(kb.x), kp1 = pk1(kb.y), kp2 = pk1(kb.z), kp3 = pk1(kb.w);
                ulonglong2 qa = *(ulonglong2*)&QsT[(kk + d) * LDQ + r0];
                ulonglong2 qb = *(ulonglong2*)&QsT[(kk + d) * LDQ + r0 + 4];
                u64 qp[4] = {qa.x, qa.y, qb.x, qb.y};
                #pragma unroll
                for (int p = 0; p < 4; p++) {
                    sp[p][0] = ffma2(qp[p], kp0, sp[p][0]);
                    sp[p][1] = ffma2(qp[p], kp1, sp[p][1]);
                    sp[p][2] = ffma2(qp[p], kp2, sp[p][2]);
                    sp[p][3] = ffma2(qp[p], kp3, sp[p][3]);
                }
            }
        }

        float sx[8][4];
        #pragma unroll
        for (int p = 0; p < 4; p++)
            #pragma unroll
            for (int j = 0; j < 4; j++) {
                float2 t = up2(sp[p][j]);
                sx[2 * p + 0][j] = t.x;
                sx[2 * p + 1][j] = t.y;
            }

        #pragma unroll
        for (int i = 0; i < 8; i++)
            #pragma unroll
            for (int j = 0; j < 4; j++)
                if (!((mrow >> i) & (mcol >> j) & 1u)) sx[i][j] = -1e31f;

        float rmax[8];
        #pragma unroll
        for (int i = 0; i < 8; i++)
            rmax[i] = fmaxf(fmaxf(sx[i][0], sx[i][1]), fmaxf(sx[i][2], sx[i][3]));
        #pragma unroll
        for (int msk = 1; msk < 16; msk <<= 1)
            #pragma unroll
            for (int i = 0; i < 8; i++)
                rmax[i] = fmaxf(rmax[i], __shfl_xor_sync(0xffffffffu, rmax[i], msk));

        float rsum[8], scl[8];
        #pragma unroll
        for (int i = 0; i < 8; i++) {
            float mn = fmaxf(m_run[i], rmax[i]);
            scl[i]   = __expf(m_run[i] - mn);
            m_run[i] = mn;
            float sr = 0.f;
            #pragma unroll
            for (int j = 0; j < 4; j++) {
                sx[i][j] = __expf(sx[i][j] - mn);
                sr += sx[i][j];
            }
            rsum[i] = sr;
        }
        #pragma unroll
        for (int msk = 1; msk < 16; msk <<= 1)
            #pragma unroll
            for (int i = 0; i < 8; i++)
                rsum[i] += __shfl_xor_sync(0xffffffffu, rsum[i], msk);
        #pragma unroll
        for (int i = 0; i < 8; i++)
            l_run[i] = l_run[i] * scl[i] + rsum[i];
        #pragma unroll
        for (int p = 0; p < 4; p++) {
            u64 sc = pk2(scl[2 * p], scl[2 * p + 1]);
            #pragma unroll
            for (int j = 0; j < 4; j++) accp[p][j] = fmul2(accp[p][j], sc);
        }

        #pragma unroll
        for (int j = 0; j < 4; j++) {
            const int key = c0 + j;
            #pragma unroll
            for (int p = 0; p < 4; p++) {
                int g   = (2 * ty + (p >> 1)) ^ (tx & 7);
                int col = (g << 2) | ((p & 1) * 2);
                *(u64*)&PsT[key * LDQ + col] = pk2(sx[2 * p][j], sx[2 * p + 1][j]);
            }
        }
        __syncwarp();

        #pragma unroll 4
        for (int kk = 0; kk < KT; kk += 4) {
            const int swl = (kk >> 2) & 7;
            #pragma unroll
            for (int l = 0; l < 4; l++) {
                float4 vb = *(float4*)&Vs[(kk + l) * LDS_ + c0];
                u64 vp0 = pk1(vb.x), vp1 = pk1(vb.y), vp2 = pk1(vb.z), vp3 = pk1(vb.w);
                int g0 = ((2 * ty + 0) ^ swl) << 2;
                int g1 = ((2 * ty + 1) ^ swl) << 2;
                ulonglong2 pa = *(ulonglong2*)&PsT[(kk + l) * LDQ + g0];
                ulonglong2 pb = *(ulonglong2*)&PsT[(kk + l) * LDQ + g1];
                u64 pp[4] = {pa.x, pa.y, pb.x, pb.y};
                #pragma unroll
                for (int p = 0; p < 4; p++) {
                    accp[p][0] = ffma2(pp[p], vp0, accp[p][0]);
                    accp[p][1] = ffma2(pp[p], vp1, accp[p][1]);
                    accp[p][2] = ffma2(pp[p], vp2, accp[p][2]);
                    accp[p][3] = ffma2(pp[p], vp3, accp[p][3]);
                }
            }
        }
    }

    #pragma unroll
    for (int p = 0; p < 4; p++) {
        float2 a0 = up2(accp[p][0]);
        float2 a1 = up2(accp[p][1]);
        float2 a2 = up2(accp[p][2]);
        float2 a3 = up2(accp[p][3]);
        float inv0 = 1.0f / l_run[2 * p + 0];
        float inv1 = 1.0f / l_run[2 * p + 1];
        float4 rlo = make_float4(a0.x * inv0, a1.x * inv0, a2.x * inv0, a3.x * inv0);
        float4 rhi = make_float4(a0.y * inv1, a1.y * inv1, a2.y * inv1, a3.y * inv1);
        *(float4*)(outp + (size_t)(b * S_LEN + q0 + r0 + 2 * p + 0) * DMODEL + h * HD + c0) = rlo;
        *(float4*)(outp + (size_t)(b * S_LEN + q0 + r0 + 2 * p + 1) * DMODEL + h * HD + c0) = rhi;
    }
}

// ---------------------------------------------------------------------------
extern "C" void kernel_launch(void* const* d_in, const int* in_sizes, int n_in,
                              void* d_out, int out_size)
{
    (void)in_sizes; (void)n_in; (void)out_size;
    const float* toks  = (const float*)d_in[0];
    const int*   masks = (const int*)  d_in[1];
    const float* Wq    = (const float*)d_in[2];
    const float* bq    = (const float*)d_in[3];
    const float* Wk    = (const float*)d_in[4];
    const float* bk    = (const float*)d_in[5];
    const float* Wv    = (const float*)d_in[6];
    const float* bv    = (const float*)d_in[7];
    float* outp = (float*)d_out;

    cudaFuncSetAttribute(qkv_mma_kernel,
                         cudaFuncAttributeMaxDynamicSharedMemorySize, GSMEM_B);
    const int attn_smem = (64 * LDQ + KT * LDS_ + KT * LDS_ + 64 * LDQ) * (int)sizeof(float);
    cudaFuncSetAttribute(attn_kernel,
                         cudaFuncAttributeMaxDynamicSharedMemorySize, attn_smem);

    split_toks_kernel<<<(MTOT * DMODEL) / (256 * 4), 256>>>(toks);
    transpose_split_w_kernel<<<dim3(DMODEL / 32, DMODEL / 32, 3), dim3(32, 8)>>>(Wq, Wk, Wv);
    qkv_mma_kernel<<<dim3(MTOT / 128, DMODEL / 128, 3), 256, GSMEM_B>>>(bq, bk, bv);
    attn_kernel<<<dim3(S_LEN / QT, NHEADS, 4), 256, attn_smem>>>(masks, outp);
}